// round 5
// baseline (speedup 1.0000x reference)
#include <cuda_runtime.h>
#include <cuda_bf16.h>

// SNN bit-plane quantization scan.
// x: [T*B, TOK, DIM] fp32, viewed as [T, N] with N = B*TOK*DIM.
// Per neuron n:
//   mem = lam/2
//   for t in 0..T-1:
//     mem += x[t, n]
//     k = clamp( trunc(mem * 128 / lam), 0, 255 )   // matches astype(int32)+clip
//     spike = lam * k      // == sum over bit planes of lam*2^j*bit_j (exact recombination)
//     out[t, n] = spike
//     mem -= spike
//
// Pure streaming: read 77MB + write 77MB -> HBM-bound. Loads for all T=4
// timesteps are issued up-front (MLP_p1=4) to overlap DRAM latency.

#define T_STEPS 4

__device__ __forceinline__ float snn_step(float& m, float lam) {
    // exact op order as reference: (mem * scale) / lam, truncate toward zero, clamp
    int k = (int)((m * 128.0f) / lam);
    k = min(max(k, 0), 255);
    float spike = lam * (float)k;
    m -= spike;
    return spike;
}

__global__ __launch_bounds__(256) void snn_scan_kernel(
    const float4* __restrict__ x,
    const float* __restrict__ lam_p,
    float4* __restrict__ out,
    int n4)  // N / 4 elements per timestep (in float4 units)
{
    int i = blockIdx.x * blockDim.x + threadIdx.x;
    if (i >= n4) return;

    const float lam = __ldg(lam_p);
    const float m0 = 0.5f * lam;

    // Batch all T loads first: 4 independent LDG.128 in flight per thread.
    float4 xv[T_STEPS];
#pragma unroll
    for (int t = 0; t < T_STEPS; t++)
        xv[t] = x[t * n4 + i];

    float4 m = make_float4(m0, m0, m0, m0);
    float4 s[T_STEPS];
#pragma unroll
    for (int t = 0; t < T_STEPS; t++) {
        m.x += xv[t].x;
        m.y += xv[t].y;
        m.z += xv[t].z;
        m.w += xv[t].w;
        s[t].x = snn_step(m.x, lam);
        s[t].y = snn_step(m.y, lam);
        s[t].z = snn_step(m.z, lam);
        s[t].w = snn_step(m.w, lam);
    }

#pragma unroll
    for (int t = 0; t < T_STEPS; t++)
        out[t * n4 + i] = s[t];
}

extern "C" void kernel_launch(void* const* d_in, const int* in_sizes, int n_in,
                              void* d_out, int out_size) {
    const float* x   = (const float*)d_in[0];
    const float* lam = (const float*)d_in[1];
    float* out       = (float*)d_out;

    int total = in_sizes[0];          // T * B * TOK * DIM
    int n_per_t = total / T_STEPS;    // B * TOK * DIM = 4,816,896 (divisible by 4)
    int n4 = n_per_t / 4;             // 1,204,224 float4 elements per timestep

    int block = 256;
    int grid = (n4 + block - 1) / block;
    snn_scan_kernel<<<grid, block>>>(
        (const float4*)x, lam, (float4*)out, n4);
}